// round 7
// baseline (speedup 1.0000x reference)
#include <cuda_runtime.h>
#include <cstdint>
#include <math.h>

// Problem constants
#define B_   8
#define T_   4
#define C_   512
#define H_   32
#define W_   32
#define HW_  1024
#define BT_  32          // B_*T_
#define NPART 32         // channel partitions per t
#define CPP   (C_/NPART) // 16 channels per block
#define DEPTH 3          // cp.async pipeline depth (smem slots)
#define HP_  28
#define WP_  28
#define NP_  784         // 28*28
#define BN_EPS 1e-5f
#define BSTRIDE ((size_t)T_ * C_ * HW_)   // elements between consecutive b

// Per-slot smem: l = 2048 float4 (32KB), r = 2048 float4 (32KB)
#define SLOT_F4   4096                    // float4 per slot (l then r)
#define SMEM_DYN  (DEPTH * SLOT_F4 * 16)  // 196608 bytes

// Scratch (allocation-free rule: __device__ globals)
__device__ float g_part[NPART][BT_ * HW_];   // 4 MB
__device__ float g_d2[BT_ * HW_];            // 128 KB

__device__ __forceinline__ void cp_async16(unsigned int smem_dst, const void* gsrc) {
    asm volatile("cp.async.cg.shared.global [%0], [%1], 16;\n"
                 :: "r"(smem_dst), "l"(gsrc));
}
__device__ __forceinline__ void cp_commit() {
    asm volatile("cp.async.commit_group;\n" ::: "memory");
}
__device__ __forceinline__ void cp_wait2() {
    asm volatile("cp.async.wait_group 2;\n" ::: "memory");
}

// ---------------------------------------------------------------------------
// Fused kernel: ONE pass over the tensors, cp.async 3-deep smem pipeline.
// grid: T_*NPART = 128 blocks (1/SM, single wave), 1024 threads.
// Block (t,p) owns 16 channels. Each thread cp.asyncs exactly the 4 float4
// it later consumes (own-data -> no barrier needed for tile data).
// One __syncthreads per channel (warp-sum combine, parity double-buffered).
// beta cancels exactly in (l_bn - r_bn).
// ---------------------------------------------------------------------------
__global__ __launch_bounds__(1024, 1) void fused_kernel(
    const float* __restrict__ l, const float* __restrict__ r,
    const float* __restrict__ gamma)
{
    extern __shared__ float4 ring[];   // DEPTH slots of [l:2048 | r:2048] float4

    const int t   = blockIdx.x >> 5;        // / NPART
    const int p   = blockIdx.x & (NPART-1);
    const int tid = threadIdx.x;
    const int lane = tid & 31;
    const int wid  = tid >> 5;

    // float4-slot mapping: slot in [0,2048): b = slot>>8, hw4 = slot&255
    const int ba = tid >> 8,          ra_ = tid & 255;
    const int bb = (tid + 1024) >> 8, rb_ = tid & 255;

    __shared__ float w0[2][32], w1[2][32], w2[2][32], w3[2][32];
    __shared__ float sgamma[CPP];
    if (tid < CPP) sgamma[tid] = gamma[p * CPP + tid];

    float acc[8];
    #pragma unroll
    for (int k = 0; k < 8; k++) acc[k] = 0.f;

    const float4* l4 = reinterpret_cast<const float4*>(l);
    const float4* r4 = reinterpret_cast<const float4*>(r);
    const size_t offA = (size_t)ba * (BSTRIDE/4) + ra_;
    const size_t offB = (size_t)bb * (BSTRIDE/4) + rb_;
    const size_t ch0  = ((size_t)(t * C_ + p * CPP)) * (HW_/4);

    // smem byte addresses for this thread within a slot
    unsigned int ring_base;
    asm("{ .reg .u64 tmp; cvta.to.shared.u64 tmp, %1; cvt.u32.u64 %0, tmp; }"
        : "=r"(ring_base) : "l"(ring));
    const unsigned int dLa = (unsigned int)tid * 16u;                 // l, slot-rel
    const unsigned int dLb = (unsigned int)(tid + 1024) * 16u;
    const unsigned int dRa = (unsigned int)(tid + 2048) * 16u;        // r, slot-rel
    const unsigned int dRb = (unsigned int)(tid + 3072) * 16u;

    // prologue: issue channels 0..DEPTH-2
    #pragma unroll
    for (int d = 0; d < DEPTH - 1; d++) {
        const size_t ch = ch0 + (size_t)d * (HW_/4);
        const unsigned int sb = ring_base + (unsigned int)d * (SLOT_F4 * 16);
        cp_async16(sb + dLa, l4 + offA + ch);
        cp_async16(sb + dLb, l4 + offB + ch);
        cp_async16(sb + dRa, r4 + offA + ch);
        cp_async16(sb + dRb, r4 + offB + ch);
        cp_commit();
    }

    #pragma unroll
    for (int ci = 0; ci < CPP; ci++) {
        // ---- issue channel ci+DEPTH-1 (or an empty group to keep count fixed)
        if (ci + DEPTH - 1 < CPP) {
            const int d = (ci + DEPTH - 1) % DEPTH;
            const size_t ch = ch0 + (size_t)(ci + DEPTH - 1) * (HW_/4);
            const unsigned int sb = ring_base + (unsigned int)d * (SLOT_F4 * 16);
            cp_async16(sb + dLa, l4 + offA + ch);
            cp_async16(sb + dLb, l4 + offB + ch);
            cp_async16(sb + dRa, r4 + offA + ch);
            cp_async16(sb + dRb, r4 + offB + ch);
        }
        cp_commit();
        cp_wait2();        // oldest group (channel ci) complete for this thread

        // ---- read own data from smem slot ci%DEPTH
        const unsigned int sb = ring_base + (unsigned int)(ci % DEPTH) * (SLOT_F4 * 16);
        float4 lva, lvb, rva, rvb;
        asm volatile("ld.shared.v4.f32 {%0,%1,%2,%3}, [%4];"
            : "=f"(lva.x), "=f"(lva.y), "=f"(lva.z), "=f"(lva.w) : "r"(sb + dLa));
        asm volatile("ld.shared.v4.f32 {%0,%1,%2,%3}, [%4];"
            : "=f"(lvb.x), "=f"(lvb.y), "=f"(lvb.z), "=f"(lvb.w) : "r"(sb + dLb));
        asm volatile("ld.shared.v4.f32 {%0,%1,%2,%3}, [%4];"
            : "=f"(rva.x), "=f"(rva.y), "=f"(rva.z), "=f"(rva.w) : "r"(sb + dRa));
        asm volatile("ld.shared.v4.f32 {%0,%1,%2,%3}, [%4];"
            : "=f"(rvb.x), "=f"(rvb.y), "=f"(rvb.z), "=f"(rvb.w) : "r"(sb + dRb));

        // ---- per-thread partial sums
        float sl = (lva.x + lva.y) + (lva.z + lva.w)
                 + (lvb.x + lvb.y) + (lvb.z + lvb.w);
        float sr = (rva.x + rva.y) + (rva.z + rva.w)
                 + (rvb.x + rvb.y) + (rvb.z + rvb.w);
        float ql = 0.f, qr = 0.f;
        ql = fmaf(lva.x, lva.x, ql); ql = fmaf(lva.y, lva.y, ql);
        ql = fmaf(lva.z, lva.z, ql); ql = fmaf(lva.w, lva.w, ql);
        ql = fmaf(lvb.x, lvb.x, ql); ql = fmaf(lvb.y, lvb.y, ql);
        ql = fmaf(lvb.z, lvb.z, ql); ql = fmaf(lvb.w, lvb.w, ql);
        qr = fmaf(rva.x, rva.x, qr); qr = fmaf(rva.y, rva.y, qr);
        qr = fmaf(rva.z, rva.z, qr); qr = fmaf(rva.w, rva.w, qr);
        qr = fmaf(rvb.x, rvb.x, qr); qr = fmaf(rvb.y, rvb.y, qr);
        qr = fmaf(rvb.z, rvb.z, qr); qr = fmaf(rvb.w, rvb.w, qr);

        #pragma unroll
        for (int o = 16; o > 0; o >>= 1) {
            sl += __shfl_xor_sync(0xffffffffu, sl, o);
            ql += __shfl_xor_sync(0xffffffffu, ql, o);
            sr += __shfl_xor_sync(0xffffffffu, sr, o);
            qr += __shfl_xor_sync(0xffffffffu, qr, o);
        }
        const int par = ci & 1;
        if (lane == 0) {
            w0[par][wid] = sl; w1[par][wid] = ql;
            w2[par][wid] = sr; w3[par][wid] = qr;
        }
        __syncthreads();    // the ONLY barrier per channel

        // ---- every warp redundantly combines the 32 warp-sums
        float a0 = w0[par][lane], a1 = w1[par][lane];
        float a2 = w2[par][lane], a3 = w3[par][lane];
        #pragma unroll
        for (int o = 16; o > 0; o >>= 1) {
            a0 += __shfl_xor_sync(0xffffffffu, a0, o);
            a1 += __shfl_xor_sync(0xffffffffu, a1, o);
            a2 += __shfl_xor_sync(0xffffffffu, a2, o);
            a3 += __shfl_xor_sync(0xffffffffu, a3, o);
        }
        const float inv_n = 1.f / (float)(B_ * HW_);   // 1/8192
        float mul  = a0 * inv_n;
        float mur  = a2 * inv_n;
        float varl = fmaf(-mul, mul, a1 * inv_n);
        float varr = fmaf(-mur, mur, a3 * inv_n);
        float g  = sgamma[ci];
        float A  = g / sqrtf(varl + BN_EPS);
        float Bc = g / sqrtf(varr + BN_EPS);
        float D  = A * mul - Bc * mur;

        // ---- accumulate d^2 from registers
        float d;
        d = A*lva.x - Bc*rva.x - D; acc[0] = fmaf(d, d, acc[0]);
        d = A*lva.y - Bc*rva.y - D; acc[1] = fmaf(d, d, acc[1]);
        d = A*lva.z - Bc*rva.z - D; acc[2] = fmaf(d, d, acc[2]);
        d = A*lva.w - Bc*rva.w - D; acc[3] = fmaf(d, d, acc[3]);
        d = A*lvb.x - Bc*rvb.x - D; acc[4] = fmaf(d, d, acc[4]);
        d = A*lvb.y - Bc*rvb.y - D; acc[5] = fmaf(d, d, acc[5]);
        d = A*lvb.z - Bc*rvb.z - D; acc[6] = fmaf(d, d, acc[6]);
        d = A*lvb.w - Bc*rvb.w - D; acc[7] = fmaf(d, d, acc[7]);
    }

    // ---- write partials: g_part[p][(b*T+t)*1024 + hw] as float4
    float4* gp = reinterpret_cast<float4*>(g_part[p]);
    gp[(ba * T_ + t) * (HW_/4) + ra_] = make_float4(acc[0], acc[1], acc[2], acc[3]);
    gp[(bb * T_ + t) * (HW_/4) + rb_] = make_float4(acc[4], acc[5], acc[6], acc[7]);
}

// ---------------------------------------------------------------------------
// Reduce: collapse 32 partials -> g_d2. grid: 256 blocks (bt x 8 segments),
// 1024 threads as (kg = tid>>7, hw_local = tid&127). Deterministic order.
// ---------------------------------------------------------------------------
__global__ __launch_bounds__(1024) void reduce_kernel()
{
    const int bt = blockIdx.x >> 3;
    const int q  = blockIdx.x & 7;
    const int hw_local = threadIdx.x & 127;
    const int kg = threadIdx.x >> 7;          // 0..7
    const int hw = q * 128 + hw_local;

    float s = 0.f;
    #pragma unroll
    for (int i = 0; i < 4; i++)
        s += g_part[kg * 4 + i][bt * HW_ + hw];

    __shared__ float red[8][128];
    red[kg][hw_local] = s;
    __syncthreads();

    if (kg == 0) {
        float tot = 0.f;
        #pragma unroll
        for (int k = 0; k < 8; k++) tot += red[k][hw_local];
        g_d2[bt * HW_ + hw] = tot;
    }
}

// ---------------------------------------------------------------------------
// Finalize: 5x5 window sum, sqrt, max + first-argmin.
// grid: 32 blocks (one per (b,t)), 1024 threads.
// Output layout (float32, tuple order):
//   [0,32) values (B,T) | [32,96) coords (B,T,2) [x,y] | [96,25184) heatmap
// ---------------------------------------------------------------------------
__global__ __launch_bounds__(1024) void finalize_kernel(float* __restrict__ out)
{
    const int bt  = blockIdx.x;
    const int tid = threadIdx.x;

    __shared__ float d2[HW_];
    d2[tid] = g_d2[bt * HW_ + tid];
    __syncthreads();

    float mymax = -3.0e38f;
    float mymin =  3.0e38f;
    int   myidx = 0x7fffffff;

    if (tid < NP_) {
        const int y = tid / WP_;
        const int x = tid % WP_;
        float ws = 0.f;
        #pragma unroll
        for (int dy = 0; dy < 5; dy++)
            #pragma unroll
            for (int dx = 0; dx < 5; dx++)
                ws += d2[(y + dy) * W_ + (x + dx)];
        float hm = sqrtf(ws / 25.0f);
        out[96 + bt * NP_ + tid] = hm;
        mymax = hm; mymin = hm; myidx = tid;
    }

    __shared__ float smx[1024];
    __shared__ float smn[1024];
    __shared__ int   six[1024];
    smx[tid] = mymax; smn[tid] = mymin; six[tid] = myidx;
    __syncthreads();
    for (int st = 512; st > 0; st >>= 1) {
        if (tid < st) {
            smx[tid] = fmaxf(smx[tid], smx[tid + st]);
            float v = smn[tid + st];
            int  ix = six[tid + st];
            if (v < smn[tid] || (v == smn[tid] && ix < six[tid])) {
                smn[tid] = v; six[tid] = ix;
            }
        }
        __syncthreads();
    }

    if (tid == 0) {
        out[bt] = smx[0];
        int idx = six[0];
        out[32 + bt * 2 + 0] = (float)(idx % WP_);  // x_argmin
        out[32 + bt * 2 + 1] = (float)(idx / WP_);  // y_argmin
    }
}

// ---------------------------------------------------------------------------
extern "C" void kernel_launch(void* const* d_in, const int* in_sizes, int n_in,
                              void* d_out, int out_size)
{
    const float* l     = (const float*)d_in[0];
    const float* r     = (const float*)d_in[1];
    const float* gamma = (const float*)d_in[2];
    // d_in[3] = bn_beta: cancels exactly in (l_bn - r_bn), unused.
    float* out = (float*)d_out;

    static bool attr_set = false;
    if (!attr_set) {
        cudaFuncSetAttribute(fused_kernel,
            cudaFuncAttributeMaxDynamicSharedMemorySize, SMEM_DYN);
        attr_set = true;
    }

    fused_kernel<<<T_ * NPART, 1024, SMEM_DYN>>>(l, r, gamma);
    reduce_kernel<<<BT_ * 8, 1024>>>();
    finalize_kernel<<<BT_, 1024>>>(out);
}

// round 9
// speedup vs baseline: 1.0785x; 1.0785x over previous
#include <cuda_runtime.h>
#include <cstdint>
#include <math.h>

// Problem constants
#define B_   8
#define T_   4
#define C_   512
#define H_   32
#define W_   32
#define HW_  1024
#define BT_  32          // B_*T_
#define NPART 64         // channel partitions per t
#define CPP   (C_/NPART) // 8 channels per block
#define HP_  28
#define WP_  28
#define NP_  784         // 28*28
#define BN_EPS 1e-5f
#define BSTRIDE ((size_t)T_ * C_ * HW_)   // elements between consecutive b
#define BSTR4   (BSTRIDE/4)               // in float4 units
#define NTHR 512

// Scratch (allocation-free rule: __device__ globals)
__device__ float g_part[NPART][BT_ * HW_];   // 8 MB
__device__ float g_d2[BT_ * HW_];            // 128 KB

// ---------------------------------------------------------------------------
// Fused kernel: ONE DRAM pass + per-channel hot-L2 re-read.
// grid: T_*NPART = 256 blocks (2/SM on most SMs), 512 threads, ~48 regs.
// Block (t,p) owns 8 channels. Per channel:
//   stats: each thread streams its 4 float4 per tensor, accumulates
//          (sum, sumsq) x2, warp shuffle-reduce, lane0 -> smem
//   ONE barrier (parity double-buffered warp-sum arrays)
//   every warp combines 16 warp-sums via shuffles, computes A,B,D
//   d^2:  re-load the SAME 4+4 float4 from L2 (just streamed -> hot),
//         accumulate d^2 into 16 register accumulators.
// Two blocks per SM de-phase and cover each other's barrier gaps.
// beta cancels exactly in (l_bn - r_bn).
// ---------------------------------------------------------------------------
__global__ __launch_bounds__(NTHR, 2) void fused_kernel(
    const float* __restrict__ l, const float* __restrict__ r,
    const float* __restrict__ gamma)
{
    const int t   = blockIdx.x >> 6;        // / NPART
    const int p   = blockIdx.x & (NPART-1);
    const int tid = threadIdx.x;
    const int lane = tid & 31;
    const int wid  = tid >> 5;              // 0..15

    // This thread's 4 float4 slots: s_i = tid + i*512, i=0..3; slot -> (b, hw4)
    int bvec[4], hw4[4];
    size_t offb[4];
    #pragma unroll
    for (int i = 0; i < 4; i++) {
        const int s = tid + i * NTHR;
        bvec[i] = s >> 8;
        hw4[i]  = s & 255;
        offb[i] = (size_t)bvec[i] * BSTR4 + hw4[i];
    }

    __shared__ float w0[2][16], w1[2][16], w2[2][16], w3[2][16];
    __shared__ float sgamma[CPP];
    if (tid < CPP) sgamma[tid] = gamma[p * CPP + tid];

    float acc[16];
    #pragma unroll
    for (int k = 0; k < 16; k++) acc[k] = 0.f;

    const float4* l4 = reinterpret_cast<const float4*>(l);
    const float4* r4 = reinterpret_cast<const float4*>(r);

    #pragma unroll 1
    for (int ci = 0; ci < CPP; ci++) {
        const int c = p * CPP + ci;
        const size_t chbase = ((size_t)(t * C_ + c)) * (HW_ / 4);

        // ---- stats pass: stream 4+4 float4, accumulate
        float sl = 0.f, ql = 0.f, sr = 0.f, qr = 0.f;
        #pragma unroll
        for (int i = 0; i < 4; i++) {
            float4 lv = l4[offb[i] + chbase];
            float4 rv = r4[offb[i] + chbase];
            sl += (lv.x + lv.y) + (lv.z + lv.w);
            sr += (rv.x + rv.y) + (rv.z + rv.w);
            ql = fmaf(lv.x, lv.x, ql); ql = fmaf(lv.y, lv.y, ql);
            ql = fmaf(lv.z, lv.z, ql); ql = fmaf(lv.w, lv.w, ql);
            qr = fmaf(rv.x, rv.x, qr); qr = fmaf(rv.y, rv.y, qr);
            qr = fmaf(rv.z, rv.z, qr); qr = fmaf(rv.w, rv.w, qr);
        }

        // ---- warp shuffle reduction
        #pragma unroll
        for (int o = 16; o > 0; o >>= 1) {
            sl += __shfl_xor_sync(0xffffffffu, sl, o);
            ql += __shfl_xor_sync(0xffffffffu, ql, o);
            sr += __shfl_xor_sync(0xffffffffu, sr, o);
            qr += __shfl_xor_sync(0xffffffffu, qr, o);
        }

        const int par = ci & 1;
        if (lane == 0) {
            w0[par][wid] = sl; w1[par][wid] = ql;
            w2[par][wid] = sr; w3[par][wid] = qr;
        }
        __syncthreads();   // the ONLY barrier per channel

        // ---- every warp combines the 16 warp-sums (lanes 0..15 hold data)
        float a0 = (lane < 16) ? w0[par][lane] : 0.f;
        float a1 = (lane < 16) ? w1[par][lane] : 0.f;
        float a2 = (lane < 16) ? w2[par][lane] : 0.f;
        float a3 = (lane < 16) ? w3[par][lane] : 0.f;
        #pragma unroll
        for (int o = 8; o > 0; o >>= 1) {
            a0 += __shfl_xor_sync(0xffffffffu, a0, o);
            a1 += __shfl_xor_sync(0xffffffffu, a1, o);
            a2 += __shfl_xor_sync(0xffffffffu, a2, o);
            a3 += __shfl_xor_sync(0xffffffffu, a3, o);
        }
        // lanes 0..15 now hold the full sums; broadcast from lane 0
        a0 = __shfl_sync(0xffffffffu, a0, 0);
        a1 = __shfl_sync(0xffffffffu, a1, 0);
        a2 = __shfl_sync(0xffffffffu, a2, 0);
        a3 = __shfl_sync(0xffffffffu, a3, 0);

        const float inv_n = 1.f / (float)(B_ * HW_);   // 1/8192
        float mul  = a0 * inv_n;
        float mur  = a2 * inv_n;
        float varl = fmaf(-mul, mul, a1 * inv_n);
        float varr = fmaf(-mur, mur, a3 * inv_n);
        float g  = sgamma[ci];
        float A  = g / sqrtf(varl + BN_EPS);
        float Bc = g / sqrtf(varr + BN_EPS);
        float D  = A * mul - Bc * mur;

        // ---- d^2 pass: re-read same data (hot in L2), accumulate
        #pragma unroll
        for (int i = 0; i < 4; i++) {
            float4 lv = l4[offb[i] + chbase];
            float4 rv = r4[offb[i] + chbase];
            float d;
            d = fmaf(A, lv.x, fmaf(-Bc, rv.x, -D)); acc[i*4+0] = fmaf(d, d, acc[i*4+0]);
            d = fmaf(A, lv.y, fmaf(-Bc, rv.y, -D)); acc[i*4+1] = fmaf(d, d, acc[i*4+1]);
            d = fmaf(A, lv.z, fmaf(-Bc, rv.z, -D)); acc[i*4+2] = fmaf(d, d, acc[i*4+2]);
            d = fmaf(A, lv.w, fmaf(-Bc, rv.w, -D)); acc[i*4+3] = fmaf(d, d, acc[i*4+3]);
        }
    }

    // ---- write partials: g_part[p][(b*T+t)*1024 + hw] as float4
    float4* gp = reinterpret_cast<float4*>(g_part[p]);
    #pragma unroll
    for (int i = 0; i < 4; i++) {
        gp[(bvec[i] * T_ + t) * (HW_/4) + hw4[i]] =
            make_float4(acc[i*4+0], acc[i*4+1], acc[i*4+2], acc[i*4+3]);
    }
}

// ---------------------------------------------------------------------------
// Reduce: collapse 64 partials -> g_d2. grid: 256 blocks (bt x 8 segments),
// 1024 threads as (kg = tid>>7 in [0,8), hw_local = tid&127). Each thread
// sums 8 partitions; smem combine of 8 groups. Deterministic order.
// ---------------------------------------------------------------------------
__global__ __launch_bounds__(1024) void reduce_kernel()
{
    const int bt = blockIdx.x >> 3;
    const int q  = blockIdx.x & 7;
    const int hw_local = threadIdx.x & 127;
    const int kg = threadIdx.x >> 7;          // 0..7
    const int hw = q * 128 + hw_local;

    float s = 0.f;
    #pragma unroll
    for (int i = 0; i < 8; i++)
        s += g_part[kg * 8 + i][bt * HW_ + hw];

    __shared__ float red[8][128];
    red[kg][hw_local] = s;
    __syncthreads();

    if (kg == 0) {
        float tot = 0.f;
        #pragma unroll
        for (int k = 0; k < 8; k++) tot += red[k][hw_local];
        g_d2[bt * HW_ + hw] = tot;
    }
}

// ---------------------------------------------------------------------------
// Finalize: 5x5 window sum, sqrt, max + first-argmin.
// grid: 32 blocks (one per (b,t)), 1024 threads.
// Output layout (float32, tuple order):
//   [0,32) values (B,T) | [32,96) coords (B,T,2) [x,y] | [96,25184) heatmap
// ---------------------------------------------------------------------------
__global__ __launch_bounds__(1024) void finalize_kernel(float* __restrict__ out)
{
    const int bt  = blockIdx.x;
    const int tid = threadIdx.x;

    __shared__ float d2[HW_];
    d2[tid] = g_d2[bt * HW_ + tid];
    __syncthreads();

    float mymax = -3.0e38f;
    float mymin =  3.0e38f;
    int   myidx = 0x7fffffff;

    if (tid < NP_) {
        const int y = tid / WP_;
        const int x = tid % WP_;
        float ws = 0.f;
        #pragma unroll
        for (int dy = 0; dy < 5; dy++)
            #pragma unroll
            for (int dx = 0; dx < 5; dx++)
                ws += d2[(y + dy) * W_ + (x + dx)];
        float hm = sqrtf(ws / 25.0f);
        out[96 + bt * NP_ + tid] = hm;
        mymax = hm; mymin = hm; myidx = tid;
    }

    __shared__ float smx[1024];
    __shared__ float smn[1024];
    __shared__ int   six[1024];
    smx[tid] = mymax; smn[tid] = mymin; six[tid] = myidx;
    __syncthreads();
    for (int st = 512; st > 0; st >>= 1) {
        if (tid < st) {
            smx[tid] = fmaxf(smx[tid], smx[tid + st]);
            float v = smn[tid + st];
            int  ix = six[tid + st];
            if (v < smn[tid] || (v == smn[tid] && ix < six[tid])) {
                smn[tid] = v; six[tid] = ix;
            }
        }
        __syncthreads();
    }

    if (tid == 0) {
        out[bt] = smx[0];
        int idx = six[0];
        out[32 + bt * 2 + 0] = (float)(idx % WP_);  // x_argmin
        out[32 + bt * 2 + 1] = (float)(idx / WP_);  // y_argmin
    }
}

// ---------------------------------------------------------------------------
extern "C" void kernel_launch(void* const* d_in, const int* in_sizes, int n_in,
                              void* d_out, int out_size)
{
    const float* l     = (const float*)d_in[0];
    const float* r     = (const float*)d_in[1];
    const float* gamma = (const float*)d_in[2];
    // d_in[3] = bn_beta: cancels exactly in (l_bn - r_bn), unused.
    float* out = (float*)d_out;

    fused_kernel<<<T_ * NPART, NTHR>>>(l, r, gamma);
    reduce_kernel<<<BT_ * 8, 1024>>>();
    finalize_kernel<<<BT_, 1024>>>(out);
}